// round 7
// baseline (speedup 1.0000x reference)
#include <cuda_runtime.h>
#include <math.h>

#define VOCAB 32000
#define NTOK  4096
#define RPB   4            // rows per block
#define NBLK  (NTOK / RPB) // 1024

// Deterministic fixed-point accumulator (2^42 scale) + completion counter.
__device__ long long g_sum   = 0;
__device__ unsigned  g_count = 0;

// ---------------------------------------------------------------------------
// One block = 4 consecutive rows, streamed interleaved (4 independent LDG.128
// per iteration -> high MLP). Irregular loads (dtype probe, targets, clamped
// speculative gathers for both int32/int64 interpretations) are all issued at
// the head by warp 0 and consumed only at the tail. Per-block tail does ONE
// fixed-point atomicAdd (order-independent => deterministic).
// ---------------------------------------------------------------------------
__global__ void __launch_bounds__(256) fused_kernel(
    const float* __restrict__ x,
    const void*  __restrict__ target_raw,
    float* __restrict__ out)
{
    const int row0 = blockIdx.x * RPB;
    const int tid  = threadIdx.x;
    const int lane = tid & 31;
    const int warp = tid >> 5;

    const int* __restrict__ t32 = (const int*)target_raw;

    // ---- head: probe + per-row target words + speculative gathers ----
    int   pv = 0, tw = 0, lo = 0, hi = 0;
    float x0 = 0.0f, xa = 0.0f, xb = 0.0f;
    if (warp == 0) {
        pv = t32[2 * lane + 1];               // odd words (int64 high OR int32 vals)
        if (lane < RPB) {
            const int r = row0 + lane;
            tw = t32[r];                      // int32 interpretation
            lo = t32[2 * r];                  // int64 low word
            hi = t32[2 * r + 1];              // int64 high word
            const size_t ro = (size_t)r * VOCAB;
            const int ca = (tw > 0 && tw < VOCAB) ? tw : 0;
            const int cb = (hi == 0 && lo > 0 && lo < VOCAB) ? lo : 0;
            x0 = x[ro];
            xa = x[ro + (size_t)ca];
            xb = x[ro + (size_t)cb];
        }
    }

    // ---- interleaved 4-row stream (rows contiguous in memory) ----
    const float4* __restrict__ p =
        reinterpret_cast<const float4*>(x + (size_t)row0 * VOCAB);
    float s0 = 0.0f, s1 = 0.0f, s2 = 0.0f, s3 = 0.0f;
    #pragma unroll 2
    for (int i = tid; i < 8000; i += 256) {
        float4 v0 = p[i];
        float4 v1 = p[i +  8000];
        float4 v2 = p[i + 16000];
        float4 v3 = p[i + 24000];
        s0 += (v0.x + v0.y) + (v0.z + v0.w);
        s1 += (v1.x + v1.y) + (v1.z + v1.w);
        s2 += (v2.x + v2.y) + (v2.z + v2.w);
        s3 += (v3.x + v3.y) + (v3.z + v3.w);
    }

    // ---- per-warp reduce of all 4 sums ----
    #pragma unroll
    for (int o = 16; o > 0; o >>= 1) {
        s0 += __shfl_xor_sync(0xFFFFFFFFu, s0, o);
        s1 += __shfl_xor_sync(0xFFFFFFFFu, s1, o);
        s2 += __shfl_xor_sync(0xFFFFFFFFu, s2, o);
        s3 += __shfl_xor_sync(0xFFFFFFFFu, s3, o);
    }
    __shared__ float4 wsum4[8];
    if (lane == 0) wsum4[warp] = make_float4(s0, s1, s2, s3);
    __syncthreads();

    if (warp == 0) {
        // cross-warp reduce (8 partials)
        float4 w = make_float4(0.f, 0.f, 0.f, 0.f);
        if (lane < 8) w = wsum4[lane];
        #pragma unroll
        for (int o = 4; o > 0; o >>= 1) {
            w.x += __shfl_xor_sync(0xFFFFFFFFu, w.x, o);
            w.y += __shfl_xor_sync(0xFFFFFFFFu, w.y, o);
            w.z += __shfl_xor_sync(0xFFFFFFFFu, w.z, o);
            w.w += __shfl_xor_sync(0xFFFFFFFFu, w.w, o);
        }
        // broadcast row sums from lane 0
        const float S0 = __shfl_sync(0xFFFFFFFFu, w.x, 0);
        const float S1 = __shfl_sync(0xFFFFFFFFu, w.y, 0);
        const float S2 = __shfl_sync(0xFFFFFFFFu, w.z, 0);
        const float S3 = __shfl_sync(0xFFFFFFFFu, w.w, 0);

        // resolve dtype: all 32 odd words zero <=> int64
        const unsigned nz = __ballot_sync(0xFFFFFFFFu, pv != 0);
        const bool is64 = (nz == 0);

        // lanes 0..3 compute their row's loss (others contribute 0)
        long long ll = 0;
        if (lane < RPB) {
            const long long t = is64 ? ((hi == 0) ? (long long)lo : -1LL)
                                     : (long long)tw;
            if (t > 0 && t < VOCAB) {
                const float S  = (lane == 0) ? S0 : (lane == 1) ? S1
                               : (lane == 2) ? S2 : S3;
                const float xt = is64 ? xb : xa;
                const double base    = 0.1 / 31999.0;         // SMOOTHING/(V-1)
                const double LN_BASE = -12.676045024287623;   // ln(base)
                const double LN_CONF = -0.10536051565782628;  // ln(0.9)
                const double K1 = (double)(VOCAB - 2) * base * LN_BASE
                                + 0.9 * LN_CONF;
                const double loss = K1
                    - base * ((double)S - (double)x0 - (double)xt)
                    - 0.9 * (double)xt;
                ll = llrint(loss * 4398046511104.0);          // * 2^42
            }
        }
        // sum ll across warp (lanes >= 4 are 0)
        #pragma unroll
        for (int o = 16; o > 0; o >>= 1)
            ll += __shfl_xor_sync(0xFFFFFFFFu, ll, o);

        if (lane == 0) {
            atomicAdd((unsigned long long*)&g_sum, (unsigned long long)ll);
            __threadfence();
            const unsigned prev = atomicAdd(&g_count, 1u);
            if (prev == (unsigned)(gridDim.x - 1)) {
                const long long tot = *(volatile long long*)&g_sum;
                out[0] = (float)((double)tot * (1.0 / 4398046511104.0));
                g_sum = 0;      // reset for next graph replay
                g_count = 0;
            }
        }
    }
}

extern "C" void kernel_launch(void* const* d_in, const int* in_sizes, int n_in,
                              void* d_out, int out_size) {
    const float* model_output = (const float*)d_in[0];
    const void*  target       = (const void*)d_in[1];
    float* out = (float*)d_out;

    fused_kernel<<<NBLK, 256>>>(model_output, target, out);
}

// round 8
// speedup vs baseline: 1.2101x; 1.2101x over previous
#include <cuda_runtime.h>
#include <math.h>

#define VOCAB 32000
#define NTOK  4096
#define HALF  (VOCAB / 2)       // 16000 floats per half-row
#define NVEC  (HALF / 4)        // 4000 float4 per half-row
#define NBLK  (NTOK * 2)        // 8192 blocks, half row each

// Deterministic fixed-point accumulator (2^42 scale).
__device__ long long g_sum = 0;

// ---------------------------------------------------------------------------
// Hot kernel: one block = half a row (64KB stream). Contribution:
//   every half (if row valid):  -base * S_half
//   half 0 additionally:        K1 + base*(x0 + xt) - conf*xt
// Summed in 2^42 fixed point via ONE atomicAdd per block (order-independent
// integer adds => bitwise deterministic). No fence, no counter: the finalize
// kernel below is ordered by the kernel boundary.
// ---------------------------------------------------------------------------
__global__ void __launch_bounds__(256) stream_kernel(
    const float* __restrict__ x,
    const void*  __restrict__ target_raw)
{
    const int row  = blockIdx.x >> 1;
    const int half = blockIdx.x & 1;
    const size_t rowoff = (size_t)row * VOCAB;

    const int tid  = threadIdx.x;
    const int lane = tid & 31;
    const int warp = tid >> 5;

    const int* __restrict__ t32 = (const int*)target_raw;

    // Head: dtype probe + target words (independent loads, consumed at tail)
    int pv = 0, tw = 0, lo = 0, hi = 0;
    if (warp == 0) {
        pv = t32[2 * lane + 1];           // odd words: int64 high OR int32 vals
        if (lane == 0) {
            tw = t32[row];
            lo = t32[2 * row];
            hi = t32[2 * row + 1];
        }
    }

    const float4* __restrict__ p =
        reinterpret_cast<const float4*>(x + rowoff + (size_t)half * HALF);

    // ---- stream part 1 (covers target-word load latency) ----
    float s = 0.0f;
    #pragma unroll 4
    for (int i = tid; i < 1024; i += 256) {
        float4 v = p[i];
        s += (v.x + v.y) + (v.z + v.w);
    }

    // Mid-stream: speculative clamped gathers (half 0 only, lane 0 of warp 0)
    float x0 = 0.0f, xa = 0.0f, xb = 0.0f;
    if (half == 0 && warp == 0 && lane == 0) {
        const int ca = (tw > 0 && tw < VOCAB) ? tw : 0;
        const int cb = (hi == 0 && lo > 0 && lo < VOCAB) ? lo : 0;
        x0 = x[rowoff];
        xa = x[rowoff + (size_t)ca];
        xb = x[rowoff + (size_t)cb];
    }

    // ---- stream part 2 ----
    #pragma unroll 4
    for (int i = 1024 + tid; i < NVEC; i += 256) {
        float4 v = p[i];
        s += (v.x + v.y) + (v.z + v.w);
    }

    // block reduce
    #pragma unroll
    for (int o = 16; o > 0; o >>= 1)
        s += __shfl_xor_sync(0xFFFFFFFFu, s, o);
    __shared__ float wsum[8];
    if (lane == 0) wsum[warp] = s;
    __syncthreads();

    if (warp == 0) {
        float S = (lane < 8) ? wsum[lane] : 0.0f;
        #pragma unroll
        for (int o = 4; o > 0; o >>= 1)
            S += __shfl_xor_sync(0xFFFFFFFFu, S, o);

        // resolve dtype: all 32 odd words zero <=> int64
        const unsigned nz = __ballot_sync(0xFFFFFFFFu, pv != 0);

        if (lane == 0) {
            const bool is64 = (nz == 0);
            const long long t = is64 ? ((hi == 0) ? (long long)lo : -1LL)
                                     : (long long)tw;
            double contrib = 0.0;
            if (t > 0 && t < VOCAB) {
                const double base = 0.1 / 31999.0;            // SMOOTHING/(V-1)
                contrib = -base * (double)S;
                if (half == 0) {
                    const double LN_BASE = -12.676045024287623;  // ln(base)
                    const double LN_CONF = -0.10536051565782628; // ln(0.9)
                    const double K1 = (double)(VOCAB - 2) * base * LN_BASE
                                    + 0.9 * LN_CONF;
                    const float xt = is64 ? xb : xa;
                    contrib += K1 + base * ((double)x0 + (double)xt)
                                  - 0.9 * (double)xt;
                }
            }
            const long long ll = llrint(contrib * 4398046511104.0); // * 2^42
            if (ll != 0)
                atomicAdd((unsigned long long*)&g_sum, (unsigned long long)ll);
        }
    }
}

// ---------------------------------------------------------------------------
// Finalize: convert fixed point -> float, reset accumulator for graph replay.
// ---------------------------------------------------------------------------
__global__ void finalize_kernel(float* __restrict__ out) {
    if (threadIdx.x == 0) {
        const long long tot = g_sum;
        out[0] = (float)((double)tot * (1.0 / 4398046511104.0));
        g_sum = 0;
    }
}

extern "C" void kernel_launch(void* const* d_in, const int* in_sizes, int n_in,
                              void* d_out, int out_size) {
    const float* model_output = (const float*)d_in[0];
    const void*  target       = (const void*)d_in[1];
    float* out = (float*)d_out;

    stream_kernel<<<NBLK, 256>>>(model_output, target);
    finalize_kernel<<<1, 32>>>(out);
}

// round 9
// speedup vs baseline: 1.2393x; 1.0242x over previous
#include <cuda_runtime.h>
#include <math.h>

#define VOCAB 32000
#define NTOK  4096
#define HALF  (VOCAB / 2)       // 16000 floats per half-row
#define NVEC  (HALF / 4)        // 4000 float4 per half-row
#define NBLK  (NTOK * 2)        // 8192 blocks, half row each

// Packed accumulator: bits[0:14) = arrival count, bits[14:64) = fixed-point
// sum (scale 2^36). Integer adds commute exactly => deterministic.
__device__ unsigned long long g_acc = 0ULL;

#define FIXSCALE 68719476736.0   // 2^36

// ---------------------------------------------------------------------------
// One block = half a row (64KB stream). Contribution:
//   every half (if row valid):  -base * S_half
//   half 0 additionally:        K1 + base*(x0 + xt) - conf*xt
// Tail: ONE atomicAdd of ((ll << 14) | 1). The 8192nd arrival (old low-14 ==
// 8191) holds the complete sum in the returned value -> writes out[0] and
// resets g_acc. No fence, no counter, no second kernel.
// ---------------------------------------------------------------------------
__global__ void __launch_bounds__(256) fused_kernel(
    const float* __restrict__ x,
    const void*  __restrict__ target_raw,
    float* __restrict__ out)
{
    const int row  = blockIdx.x >> 1;
    const int half = blockIdx.x & 1;
    const size_t rowoff = (size_t)row * VOCAB;

    const int tid  = threadIdx.x;
    const int lane = tid & 31;
    const int warp = tid >> 5;

    const int* __restrict__ t32 = (const int*)target_raw;

    // Head: dtype probe + target words (independent loads, consumed at tail)
    int pv = 0, tw = 0, lo = 0, hi = 0;
    if (warp == 0) {
        pv = t32[2 * lane + 1];           // odd words: int64 high OR int32 vals
        if (lane == 0) {
            tw = t32[row];
            lo = t32[2 * row];
            hi = t32[2 * row + 1];
        }
    }

    const float4* __restrict__ p =
        reinterpret_cast<const float4*>(x + rowoff + (size_t)half * HALF);

    // ---- stream part 1 (covers target-word load latency) ----
    float s = 0.0f;
    #pragma unroll 4
    for (int i = tid; i < 1024; i += 256) {
        float4 v = p[i];
        s += (v.x + v.y) + (v.z + v.w);
    }

    // Mid-stream: speculative clamped gathers (half 0 only, lane 0 of warp 0)
    float x0 = 0.0f, xa = 0.0f, xb = 0.0f;
    if (half == 0 && warp == 0 && lane == 0) {
        const int ca = (tw > 0 && tw < VOCAB) ? tw : 0;
        const int cb = (hi == 0 && lo > 0 && lo < VOCAB) ? lo : 0;
        x0 = x[rowoff];
        xa = x[rowoff + (size_t)ca];
        xb = x[rowoff + (size_t)cb];
    }

    // ---- stream part 2 ----
    #pragma unroll 4
    for (int i = 1024 + tid; i < NVEC; i += 256) {
        float4 v = p[i];
        s += (v.x + v.y) + (v.z + v.w);
    }

    // block reduce
    #pragma unroll
    for (int o = 16; o > 0; o >>= 1)
        s += __shfl_xor_sync(0xFFFFFFFFu, s, o);
    __shared__ float wsum[8];
    if (lane == 0) wsum[warp] = s;
    __syncthreads();

    if (warp == 0) {
        float S = (lane < 8) ? wsum[lane] : 0.0f;
        #pragma unroll
        for (int o = 4; o > 0; o >>= 1)
            S += __shfl_xor_sync(0xFFFFFFFFu, S, o);

        // resolve dtype: all 32 odd words zero <=> int64
        const unsigned nz = __ballot_sync(0xFFFFFFFFu, pv != 0);

        if (lane == 0) {
            const bool is64 = (nz == 0);
            const long long t = is64 ? ((hi == 0) ? (long long)lo : -1LL)
                                     : (long long)tw;
            double contrib = 0.0;
            if (t > 0 && t < VOCAB) {
                const double base = 0.1 / 31999.0;            // SMOOTHING/(V-1)
                contrib = -base * (double)S;
                if (half == 0) {
                    const double LN_BASE = -12.676045024287623;  // ln(base)
                    const double LN_CONF = -0.10536051565782628; // ln(0.9)
                    const double K1 = (double)(VOCAB - 2) * base * LN_BASE
                                    + 0.9 * LN_CONF;
                    const float xt = is64 ? xb : xa;
                    contrib += K1 + base * ((double)x0 + (double)xt)
                                  - 0.9 * (double)xt;
                }
            }
            const long long ll = llrint(contrib * FIXSCALE);     // * 2^36
            const unsigned long long val =
                ((unsigned long long)ll << 14) + 1ULL;
            const unsigned long long old = atomicAdd(&g_acc, val);

            if ((old & 0x3FFFULL) == (unsigned long long)(NBLK - 1)) {
                // We are the last arrival: returned value + ours = full sum.
                const long long tot = (long long)(old + val);
                const long long sumll = (tot - (long long)NBLK) >> 14; // arith
                out[0] = (float)((double)sumll * (1.0 / FIXSCALE));
                g_acc = 0ULL;   // reset for next graph replay (same-addr order)
            }
        }
    }
}

extern "C" void kernel_launch(void* const* d_in, const int* in_sizes, int n_in,
                              void* d_out, int out_size) {
    const float* model_output = (const float*)d_in[0];
    const void*  target       = (const void*)d_in[1];
    float* out = (float*)d_out;

    fused_kernel<<<NBLK, 256>>>(model_output, target, out);
}